// round 17
// baseline (speedup 1.0000x reference)
#include <cuda_runtime.h>
#include <cuda_fp16.h>
#include <cstdint>
#include <cstddef>

#define S_LEN   2048
#define HID     3584
#define NH      28
#define NKV     4
#define HD      128
#define BATCH   2
#define M_TOK   (BATCH * S_LEN)      // 4096
#define NQKV    4608
#define SCALE_Q 0.08838834764831845f
#define LOG2E   1.4426950408889634f
#define QSC     (SCALE_Q * LOG2E)
#define GEMM_GRID 296                // 148 SMs x occ 2

// ---------------- scratch ----------------
__device__ __half g_Q[(size_t)BATCH * NH * S_LEN * HD];
__device__ __half g_K[(size_t)BATCH * NKV * S_LEN * HD];
__device__ __half g_V[(size_t)BATCH * NKV * S_LEN * HD];
__device__ __half g_attn[(size_t)M_TOK * HID];
__device__ __half g_Xh[(size_t)M_TOK * HID];
__device__ __half g_Wqkv[(size_t)NQKV * HID];
__device__ __half g_Woh[(size_t)HID * NH * HD];
__device__ float  g_bqkv[NQKV];

// ---------------- helpers ----------------
__device__ __forceinline__ void mma_f16(float* c, const uint32_t* a, const uint32_t* b) {
    asm volatile(
        "mma.sync.aligned.m16n8k16.row.col.f32.f16.f16.f32 "
        "{%0,%1,%2,%3},{%4,%5,%6,%7},{%8,%9},{%0,%1,%2,%3};"
        : "+f"(c[0]), "+f"(c[1]), "+f"(c[2]), "+f"(c[3])
        : "r"(a[0]), "r"(a[1]), "r"(a[2]), "r"(a[3]), "r"(b[0]), "r"(b[1]));
}

__device__ __forceinline__ void cp_async16(void* sdst, const void* gsrc) {
    uint32_t s;
    asm("{ .reg .u64 t; cvta.to.shared.u64 t, %1; cvt.u32.u64 %0, t; }"
        : "=r"(s) : "l"(sdst));
    asm volatile("cp.async.cg.shared.global [%0], [%1], 16;" :: "r"(s), "l"(gsrc));
}
#define CP_COMMIT() asm volatile("cp.async.commit_group;")
#define CP_WAIT(N)  asm volatile("cp.async.wait_group %0;" :: "n"(N))

__device__ __forceinline__ uint32_t smem_u32(const void* p) {
    uint32_t a;
    asm("{ .reg .u64 t; cvta.to.shared.u64 t, %1; cvt.u32.u64 %0, t; }"
        : "=r"(a) : "l"(p));
    return a;
}

__device__ __forceinline__ void ldsm_x4(uint32_t& r0, uint32_t& r1,
                                        uint32_t& r2, uint32_t& r3, uint32_t addr) {
    asm volatile("ldmatrix.sync.aligned.m8n8.x4.shared.b16 {%0,%1,%2,%3}, [%4];"
                 : "=r"(r0), "=r"(r1), "=r"(r2), "=r"(r3) : "r"(addr));
}

__device__ __forceinline__ void ldsm_x4_t(uint32_t& r0, uint32_t& r1,
                                          uint32_t& r2, uint32_t& r3, uint32_t addr) {
    asm volatile("ldmatrix.sync.aligned.m8n8.x4.trans.shared.b16 {%0,%1,%2,%3}, [%4];"
                 : "=r"(r0), "=r"(r1), "=r"(r2), "=r"(r3) : "r"(addr));
}

// ------- merged fp32 -> fp16 convert + bias concat (grid-stride) -----------
#define N4_X  (M_TOK * HID / 4)
#define N4_WQ (3584 * HID / 4)
#define N4_WK (512 * HID / 4)
#define N4_BQ (3584 / 4)
#define N4_BK (512 / 4)
#define N4_CVT (N4_X + N4_WQ + 2 * N4_WK + N4_WQ)
#define N4_TOT (N4_CVT + N4_BQ + 2 * N4_BK)
__global__ void cvt_all_kernel(const float4* __restrict__ X,  const float4* __restrict__ Wq,
                               const float4* __restrict__ Wk, const float4* __restrict__ Wv,
                               const float4* __restrict__ Wo,
                               const float4* __restrict__ bq, const float4* __restrict__ bk,
                               const float4* __restrict__ bv,
                               __half2* __restrict__ Xh, __half2* __restrict__ Wqkv,
                               __half2* __restrict__ Woh, float4* __restrict__ bqkv) {
    for (int i = blockIdx.x * blockDim.x + threadIdx.x; i < N4_TOT;
         i += gridDim.x * blockDim.x) {
        int j = i;
        if (j >= N4_CVT) {
            j -= N4_CVT;
            if (j < N4_BQ)                 bqkv[j] = bq[j];
            else if ((j -= N4_BQ) < N4_BK) bqkv[N4_BQ + j] = bk[j];
            else                           bqkv[N4_BQ + N4_BK + (j - N4_BK)] = bv[j - N4_BK];
            continue;
        }
        const float4* src;
        __half2* dst;
        if (j < N4_X)                  { src = X;  dst = Xh; }
        else if ((j -= N4_X) < N4_WQ)  { src = Wq; dst = Wqkv; }
        else if ((j -= N4_WQ) < N4_WK) { src = Wk; dst = Wqkv + 2 * (size_t)N4_WQ; }
        else if ((j -= N4_WK) < N4_WK) { src = Wv; dst = Wqkv + 2 * (size_t)(N4_WQ + N4_WK); }
        else                           { j -= N4_WK; src = Wo; dst = Woh; }
        float4 v = src[j];
        dst[2 * j]     = __floats2half2_rn(v.x, v.y);
        dst[2 * j + 1] = __floats2half2_rn(v.z, v.w);
    }
}

// -- persistent fp16 GEMM: 128x128 tile, occ 2, 3-stage, single sync/chunk --
#define GK_CHUNKS (HID / 64)   // 56
#define GS_STRIDE 72           // halves per row (64 + 8 pad)
#define GEMM_A_STG (128 * GS_STRIDE)
#define GEMM_STG_TOT (2 * GEMM_A_STG)
#define GEMM_SMEM_BYTES (3 * GEMM_STG_TOT * 2)  // 110592
template <int OUT_MODE>
__global__ __launch_bounds__(256, 2)
void gemm_f16_pipe(const __half* __restrict__ A, const __half* __restrict__ Bw,
                   const float* __restrict__ bias, float* __restrict__ outF,
                   __half* __restrict__ outQ, __half* __restrict__ outK,
                   __half* __restrict__ outV, int N, int ntiles, int nx) {
    extern __shared__ __half gsmh[];

    const int tid  = threadIdx.x;
    const int warp = tid >> 5;
    const int lane = tid & 31;
    const int wm   = warp >> 1;
    const int wn   = warp & 1;
    const int K = HID;
    const int lrow = tid >> 3, lseg = tid & 7;

    const int mi = lane >> 3, rr = lane & 7;
    uint32_t rowA[2], rowB[4];
#pragma unroll
    for (int mt = 0; mt < 2; mt++)
        rowA[mt] = ((wm * 32 + mt * 16 + (mi & 1) * 8 + rr) * GS_STRIDE + (mi >> 1) * 8) * 2;
#pragma unroll
    for (int ntp = 0; ntp < 4; ntp++)
        rowB[ntp] = ((wn * 64 + ntp * 16 + (mi >> 1) * 8 + rr) * GS_STRIDE + (mi & 1) * 8) * 2
                    + GEMM_A_STG * 2;
    const uint32_t Su = smem_u32(gsmh);

    for (int tile = blockIdx.x; tile < ntiles; tile += GEMM_GRID) {
        const int bx = tile % nx, by = tile / nx;
        const int bm = by * 128, bn = bx * 128;

        const __half* Ab = A + (size_t)(bm + lrow) * K + lseg * 8;
        const __half* Bb = Bw + (size_t)(bn + lrow) * K + lseg * 8;

        __syncthreads();   // all warps done with smem of previous tile

        float acc[2][8][4];
#pragma unroll
        for (int mt = 0; mt < 2; mt++)
#pragma unroll
            for (int nt = 0; nt < 8; nt++)
#pragma unroll
                for (int i = 0; i < 4; i++) acc[mt][nt][i] = 0.f;

        // prologue: stages 0,1
#pragma unroll
        for (int s = 0; s < 2; s++) {
            __half* dA = gsmh + s * GEMM_STG_TOT;
            __half* dB = dA + GEMM_A_STG;
#pragma unroll
            for (int i = 0; i < 4; i++) {
                cp_async16(dA + (lrow + i * 32) * GS_STRIDE + lseg * 8,
                           Ab + (size_t)(i * 32) * K + s * 64);
                cp_async16(dB + (lrow + i * 32) * GS_STRIDE + lseg * 8,
                           Bb + (size_t)(i * 32) * K + s * 64);
            }
            CP_COMMIT();
        }

        int slot = 0;
        for (int k = 0; k < GK_CHUNKS; k++) {
            if (k + 1 < GK_CHUNKS) { CP_WAIT(1); } else { CP_WAIT(0); }
            __syncthreads();

            if (k + 2 < GK_CHUNKS) {
                int ns = slot + 2; if (ns >= 3) ns -= 3;
                __half* dA = gsmh + ns * GEMM_STG_TOT;
                __half* dB = dA + GEMM_A_STG;
                int k0 = (k + 2) * 64;
#pragma unroll
                for (int i = 0; i < 4; i++) {
                    cp_async16(dA + (lrow + i * 32) * GS_STRIDE + lseg * 8,
                               Ab + (size_t)(i * 32) * K + k0);
                    cp_async16(dB + (lrow + i * 32) * GS_STRIDE + lseg * 8,
                               Bb + (size_t)(i * 32) * K + k0);
                }
                CP_COMMIT();
            }

            const uint32_t Scu = Su + slot * (GEMM_STG_TOT * 2);
#pragma unroll
            for (int kc = 0; kc < 4; kc++) {
                const uint32_t coff = kc * 32;
                uint32_t aF[2][4], bF[8][2];
#pragma unroll
                for (int mt = 0; mt < 2; mt++)
                    ldsm_x4(aF[mt][0], aF[mt][1], aF[mt][2], aF[mt][3],
                            Scu + rowA[mt] + coff);
#pragma unroll
                for (int ntp = 0; ntp < 4; ntp++) {
                    uint32_t b0, b1, b2, b3;
                    ldsm_x4(b0, b1, b2, b3, Scu + rowB[ntp] + coff);
                    bF[2 * ntp][0] = b0;     bF[2 * ntp][1] = b1;
                    bF[2 * ntp + 1][0] = b2; bF[2 * ntp + 1][1] = b3;
                }
#pragma unroll
                for (int mt = 0; mt < 2; mt++)
#pragma unroll
                    for (int nt = 0; nt < 8; nt++)
                        mma_f16(acc[mt][nt], aF[mt], bF[nt]);
            }
            slot++; if (slot >= 3) slot = 0;
        }

        __half* dstbase = outQ;
        int seg_off = 0, HX = NH;
        if (OUT_MODE == 2) {
            if (bn >= 4096)      { dstbase = outV; seg_off = 4096; HX = NKV; }
            else if (bn >= 3584) { dstbase = outK; seg_off = 3584; HX = NKV; }
        }

#pragma unroll
        for (int mt = 0; mt < 2; mt++) {
            int rbase = bm + wm * 32 + mt * 16 + (lane >> 2);
#pragma unroll
            for (int nt = 0; nt < 8; nt++) {
                int cbase = bn + wn * 64 + nt * 8 + ((lane & 3) << 1);
#pragma unroll
                for (int half = 0; half < 2; half++) {
                    int r = rbase + half * 8;
                    float v0 = acc[mt][nt][2 * half];
                    float v1 = acc[mt][nt][2 * half + 1];
                    if (OUT_MODE == 0) {
                        *(float2*)(outF + (size_t)r * N + cbase) = make_float2(v0, v1);
                    } else {
                        int lc = cbase - seg_off;
                        int h = lc >> 7, d = lc & 127;
                        int b = r >> 11, s = r & 2047;
                        __half2 hv = __floats2half2_rn(v0 + bias[cbase], v1 + bias[cbase + 1]);
                        *(__half2*)(dstbase + (((size_t)(b * HX + h) * 2048 + s) << 7) + d) = hv;
                    }
                }
            }
        }
    }
}

// ---------------- RoPE on K only (fp16 in/out) ----------------
#define KROT (BATCH * NKV * S_LEN * 64)
__global__ void ropeK_kernel(__half* __restrict__ Kx,
                             const float* __restrict__ cs, const float* __restrict__ sn) {
    int idx = blockIdx.x * blockDim.x + threadIdx.x;
    if (idx >= KROT) return;
    int d  = idx & 63;
    int s  = (idx >> 6) & (S_LEN - 1);
    int bh = idx >> 17;
    int b  = bh / NKV;
    int ci = ((b << 11) + s) * 128 + d;
    float c  = cs[ci];
    float si = sn[ci];
    __half* p = Kx + (((size_t)bh << 11) + s) * 128 + d;
    float x1 = __half2float(p[0]), x2 = __half2float(p[64]);
    p[0]  = __float2half_rn(x1 * c - x2 * si);
    p[64] = __float2half_rn(x2 * c + x1 * si);
}

// -------- fp16 flash attention (fused Q-RoPE, register P) ----------
#define FS_STRIDE 136
#define KS_OFF    17408
#define KVS_STG   (64 * 136)
#define VS_OFF    34816
#define FLASH_SMEM_BYTES ((34816 + 2 * KVS_STG) * 2)  // 104448

__global__ __launch_bounds__(256, 2)
void flash_attn_f16(const __half* __restrict__ Q, const __half* __restrict__ K,
                    const __half* __restrict__ V, const float* __restrict__ cs,
                    const float* __restrict__ sn, __half* __restrict__ Out) {
    extern __shared__ __half smh[];
    __half* Qs = smh;
    __half* Ks = smh + KS_OFF;
    __half* Vs = smh + VS_OFF;

    const int qb  = (gridDim.x - 1) - blockIdx.x;
    const int h   = blockIdx.y;
    const int b   = blockIdx.z;
    const int kvh = h / (NH / NKV);

    const int t    = threadIdx.x;
    const int w    = t >> 5;
    const int lane = t & 31;
    const int lq   = lane >> 2;
    const int lr   = lane & 3;

    const __half* Qg = Q + ((((size_t)(b * NH + h) * S_LEN) + qb * 128) << 7);
    const __half* Kg = K + (((size_t)(b * NKV + kvh) * S_LEN) << 7);
    const __half* Vg = V + (((size_t)(b * NKV + kvh) * S_LEN) << 7);
    const float* csb = cs + (((size_t)b * S_LEN + qb * 128) << 7);
    const float* snb = sn + (((size_t)b * S_LEN + qb * 128) << 7);

    const int lrow = t >> 4, lseg = t & 15;

    const int mi = lane >> 3, rr = lane & 7;
    const uint32_t rowQ = ((w * 16 + (mi & 1) * 8 + rr) * FS_STRIDE + (mi >> 1) * 8) * 2;
    uint32_t rowK[4];
#pragma unroll
    for (int ntp = 0; ntp < 4; ntp++)
        rowK[ntp] = ((ntp * 16 + (mi >> 1) * 8 + rr) * FS_STRIDE + (mi & 1) * 8) * 2;

    // prologue: issue G(0) = K(0)+V(0) first (overlaps Q rope below)
#pragma unroll
    for (int i = 0; i < 4; i++) {
        int row = lrow + i * 16;
        cp_async16(Ks + row * FS_STRIDE + lseg * 8, Kg + (row << 7) + lseg * 8);
        cp_async16(Vs + row * FS_STRIDE + lseg * 8, Vg + (row << 7) + lseg * 8);
    }
    CP_COMMIT();

    // load Q with fused RoPE (+ scale*log2e)
#pragma unroll
    for (int i = 0; i < 4; i++) {
        int slot = t + i * 256;
        int row = slot >> 3;
        int sp  = slot & 7;
        const __half* qsrc = Qg + (row << 7) + sp * 8;
        __half2 lo[4], hi[4];
        *(uint4*)lo = *(const uint4*)qsrc;
        *(uint4*)hi = *(const uint4*)(qsrc + 64);
        const float* cp = csb + (row << 7) + sp * 8;
        const float* sp_ = snb + (row << 7) + sp * 8;
        __half2 olo[4], ohi[4];
#pragma unroll
        for (int j = 0; j < 4; j++) {
            float x1a = __half2float(__low2half(lo[j]));
            float x1b = __half2float(__high2half(lo[j]));
            float x2a = __half2float(__low2half(hi[j]));
            float x2b = __half2float(__high2half(hi[j]));
            float ca = cp[2 * j], cb = cp[2 * j + 1];
            float sa = sp_[2 * j], sb = sp_[2 * j + 1];
            olo[j] = __floats2half2_rn((x1a * ca - x2a * sa) * QSC,
                                       (x1b * cb - x2b * sb) * QSC);
            ohi[j] = __floats2half2_rn((x2a * ca + x1a * sa) * QSC,
                                       (x2b * cb + x1b * sb) * QSC);
        }
        __half* qdst = Qs + row * FS_STRIDE + sp * 8;
        *(uint4*)qdst = *(uint4*)olo;
        *(uint4*)(qdst + 64) = *(uint4*)ohi;
    }

    float m0 = -1e30f, m1 = -1e30f, l0 = 0.f, l1 = 0.f;
    float oacc[16][4];
#pragma unroll
    for (int nt = 0; nt < 16; nt++)
#pragma unroll
        for (int e = 0; e < 4; e++) oacc[nt][e] = 0.f;

    const int rbaseQ = w * 16 + lq;
    const int nkb = 2 * qb + 2;

    const uint32_t Qsu = smem_u32(Qs);
    const uint32_t Ksu = smem_u32(Ks);
    const uint32_t Vsu = smem_u32(Vs);
    const uint32_t vlbase = Vsu + (((lane & 15) * FS_STRIDE + (lane >> 4) * 8) << 1);

    for (int kb = 0; kb < nkb; kb++) {
        CP_WAIT(0);
        __syncthreads();

        if (kb + 1 < nkb) {
            const int ns = (kb + 1) & 1;
            __half* dK = Ks + ns * KVS_STG;
            __half* dV = Vs + ns * KVS_STG;
            const __half* Kb = Kg + ((size_t)((kb + 1) * 64) << 7);
            const __half* Vb = Vg + ((size_t)((kb + 1) * 64) << 7);
#pragma unroll
            for (int i = 0; i < 4; i++) {
                int row = lrow + i * 16;
                cp_async16(dK + row * FS_STRIDE + lseg * 8, Kb + ((size_t)row << 7) + lseg * 8);
                cp_async16(dV + row * FS_STRIDE + lseg * 8, Vb + ((size_t)row << 7) + lseg * 8);
            }
            CP_COMMIT();
        } else {
            CP_COMMIT();
        }

        // ---- scores ----
        const uint32_t Kcu = Ksu + (kb & 1) * (KVS_STG * 2);
        float sacc[8][4];
#pragma unroll
        for (int nt = 0; nt < 8; nt++)
#pragma unroll
            for (int e = 0; e < 4; e++) sacc[nt][e] = 0.f;

#pragma unroll
        for (int kc = 0; kc < 8; kc++) {
            const uint32_t coff = kc * 32;
            uint32_t a[4];
            ldsm_x4(a[0], a[1], a[2], a[3], Qsu + rowQ + coff);
#pragma unroll
            for (int ntp = 0; ntp < 4; ntp++) {
                uint32_t b0, b1, b2, b3;
                ldsm_x4(b0, b1, b2, b3, Kcu + rowK[ntp] + coff);
                uint32_t bbA[2] = {b0, b1}, bbB[2] = {b2, b3};
                mma_f16(sacc[2 * ntp],     a, bbA);
                mma_f16(sacc[2 * ntp + 1], a, bbB);
            }
        }

        if (kb >= 2 * qb) {
            int row0 = qb * 128 + rbaseQ;
#pragma unroll
            for (int nt = 0; nt < 8; nt++) {
                int key = kb * 64 + nt * 8 + lr * 2;
                if (key     > row0)     sacc[nt][0] = -1e30f;
                if (key + 1 > row0)     sacc[nt][1] = -1e30f;
                if (key     > row0 + 8) sacc[nt][2] = -1e30f;
                if (key + 1 > row0 + 8) sacc[nt][3] = -1e30f;
            }
        }

        // ---- online softmax (base 2), P into A-fragments ----
        float mx0 = -1e30f, mx1 = -1e30f;
#pragma unroll
        for (int nt = 0; nt < 8; nt++) {
            mx0 = fmaxf(mx0, fmaxf(sacc[nt][0], sacc[nt][1]));
            mx1 = fmaxf(mx1, fmaxf(sacc[nt][2], sacc[nt][3]));
        }
        mx0 = fmaxf(mx0, __shfl_xor_sync(0xffffffffu, mx0, 1));
        mx0 = fmaxf(mx0, __shfl_xor_sync(0xffffffffu, mx0, 2));
        mx1 = fmaxf(mx1, __shfl_xor_sync(0xffffffffu, mx1, 1));
        mx1 = fmaxf(mx1, __shfl_xor_sync(0xffffffffu, mx1, 2));

        float mn0 = fmaxf(m0, mx0), mn1 = fmaxf(m1, mx1);
        float al0 = exp2f(m0 - mn0), al1 = exp2f(m1 - mn1);
        m0 = mn0; m1 = mn1;

        uint32_t aP[4][4];
        float s0 = 0.f, s1 = 0.f;
#pragma unroll
        for (int nt = 0; nt < 8; nt++) {
            float p00 = exp2f(sacc[nt][0] - mn0);
            float p01 = exp2f(sacc[nt][1] - mn0);
            float p10 = exp2f(sacc[nt][2] - mn1);
            float p11 = exp2f(sacc[nt][3] - mn1);
            s0 += p00 + p01;
            s1 += p10 + p11;
            __half2 h0 = __floats2half2_rn(p00, p01);
            __half2 h1 = __floats2half2_rn(p10, p11);
            int kc = nt >> 1, odd = (nt & 1) << 1;
            aP[kc][odd]     = *(uint32_t*)&h0;
            aP[kc][odd + 1] = *(uint32_t*)&h1;
        }
        s0 += __shfl_xor_sync(0xffffffffu, s0, 1);
        s0 += __shfl_xor_sync(0xffffffffu, s0, 2);
        s1 += __shfl_xor_sync(0xffffffffu, s1, 1);
        s1 += __shfl_xor_sync(0xffffffffu, s1, 2);
        l0 = l0 * al0 + s0;
        l1 = l1 * al1 + s1;

        if (!__all_sync(0xffffffffu, (al0 == 1.f) && (al1 == 1.f))) {
#pragma unroll
            for (int nt = 0; nt < 16; nt++) {
                oacc[nt][0] *= al0; oacc[nt][1] *= al0;
                oacc[nt][2] *= al1; oacc[nt][3] *= al1;
            }
        }

        // ---- PV ----
        const uint32_t vladdr = vlbase + (kb & 1) * (KVS_STG * 2);
#pragma unroll
        for (int kc = 0; kc < 4; kc++) {
#pragma unroll
            for (int ntp = 0; ntp < 8; ntp++) {
                uint32_t b0, b1, b2, b3;
                ldsm_x4_t(b0, b1, b2, b3,
                          vladdr + ((kc * 16 * FS_STRIDE + ntp * 16) << 1));
                uint32_t bbA[2] = {b0, b1}, bbB[2] = {b2, b3};
                mma_f16(oacc[2 * ntp],     aP[kc], bbA);
                mma_f16(oacc[2 * ntp + 1], aP[kc], bbB);
            }
        }
    }

    // ---- epilogue ----
    float inv0 = 1.f / l0, inv1 = 1.f / l1;
    size_t tok0 = (size_t)b * S_LEN + qb * 128 + rbaseQ;
    __half* d0 = Out + tok0 * HID + h * 128 + 2 * lr;
    __half* d1 = d0 + (size_t)8 * HID;
#pragma unroll
    for (int nt = 0; nt < 16; nt++) {
        *(__half2*)(d0 + nt * 8) = __floats2half2_rn(oacc[nt][0] * inv0, oacc[nt][1] * inv0);
        *(__half2*)(d1 + nt * 8) = __floats2half2_rn(oacc[nt][2] * inv1, oacc[nt][3] * inv1);
    }
}

// ---------------- launch ----------------
extern "C" void kernel_launch(void* const* d_in, const int* in_sizes, int n_in,
                              void* d_out, int out_size) {
    const float* X  = (const float*)d_in[0];
    const float* cs = (const float*)d_in[1];
    const float* sn = (const float*)d_in[2];
    // d_in[3] attention_mask: pure causal, handled analytically
    const float* Wq = (const float*)d_in[4];
    const float* bq = (const float*)d_in[5];
    const float* Wk = (const float*)d_in[6];
    const float* bk = (const float*)d_in[7];
    const float* Wv = (const float*)d_in[8];
    const float* bv = (const float*)d_in[9];
    const float* Wo = (const float*)d_in[10];
    float* out = (float*)d_out;

    __half *Qp, *Kp, *Vp, *Ap, *Xh, *Wqkv, *Woh;
    float *bqkv;
    cudaGetSymbolAddress((void**)&Qp, g_Q);
    cudaGetSymbolAddress((void**)&Kp, g_K);
    cudaGetSymbolAddress((void**)&Vp, g_V);
    cudaGetSymbolAddress((void**)&Ap, g_attn);
    cudaGetSymbolAddress((void**)&Xh, g_Xh);
    cudaGetSymbolAddress((void**)&Wqkv, g_Wqkv);
    cudaGetSymbolAddress((void**)&Woh, g_Woh);
    cudaGetSymbolAddress((void**)&bqkv, g_bqkv);

    cudaFuncSetAttribute(flash_attn_f16, cudaFuncAttributeMaxDynamicSharedMemorySize,
                         FLASH_SMEM_BYTES);
    cudaFuncSetAttribute(gemm_f16_pipe<0>, cudaFuncAttributeMaxDynamicSharedMemorySize,
                         GEMM_SMEM_BYTES);
    cudaFuncSetAttribute(gemm_f16_pipe<2>, cudaFuncAttributeMaxDynamicSharedMemorySize,
                         GEMM_SMEM_BYTES);

    cvt_all_kernel<<<2048, 256>>>((const float4*)X, (const float4*)Wq, (const float4*)Wk,
                                  (const float4*)Wv, (const float4*)Wo,
                                  (const float4*)bq, (const float4*)bk, (const float4*)bv,
                                  (__half2*)Xh, (__half2*)Wqkv, (__half2*)Woh,
                                  (float4*)bqkv);

    // fused QKV projection: persistent, 36x32 = 1152 tiles
    gemm_f16_pipe<2><<<GEMM_GRID, 256, GEMM_SMEM_BYTES>>>(
        Xh, Wqkv, bqkv, nullptr, Qp, Kp, Vp, NQKV, (NQKV / 128) * (M_TOK / 128), NQKV / 128);

    ropeK_kernel<<<KROT / 256, 256>>>(Kp, cs, sn);

    flash_attn_f16<<<dim3(S_LEN / 128, NH, BATCH), 256, FLASH_SMEM_BYTES>>>(
        Qp, Kp, Vp, cs, sn, Ap);

    // O projection: persistent, 28x32 = 896 tiles
    gemm_f16_pipe<0><<<GEMM_GRID, 256, GEMM_SMEM_BYTES>>>(
        Ap, Woh, nullptr, out, nullptr, nullptr, nullptr, HID, (HID / 128) * (M_TOK / 128), HID / 128);
}